// round 6
// baseline (speedup 1.0000x reference)
#include <cuda_runtime.h>
#include <math_constants.h>
#include <cuda_bf16.h>

// Problem constants
#define Cc    256
#define HW    4096      // H*W = 64*64
#define NPTS  65536     // B*H*W
#define KK    1024
#define NZQ   16777216  // B*C*H*W
#define NBLK  512       // grid of main kernel (NPTS / BM)
#define BM    128       // points per CTA

// Scratch (no device mallocs allowed)
__device__ float g_cnorm[KK];
__device__ float g_znorm[NPTS];
__device__ float g_partial[NBLK];

// ---------------------------------------------------------------------------
// ||c_k||^2 — replicate XLA CPU reduce: sequential ascending c,
// separate mul + add (NO fma), round-to-nearest each step.
// ---------------------------------------------------------------------------
__global__ void cnorm_kernel(const float* __restrict__ cb) {
    int k = blockIdx.x * 256 + threadIdx.x;   // grid 4 x 256 -> 1024
    const float4* row = (const float4*)(cb + (size_t)k * Cc);
    float s = 0.f;
#pragma unroll
    for (int i = 0; i < Cc / 4; ++i) {
        float4 v = row[i];
        s = __fadd_rn(s, __fmul_rn(v.x, v.x));
        s = __fadd_rn(s, __fmul_rn(v.y, v.y));
        s = __fadd_rn(s, __fmul_rn(v.z, v.z));
        s = __fadd_rn(s, __fmul_rn(v.w, v.w));
    }
    g_cnorm[k] = s;
}

// ---------------------------------------------------------------------------
// ||z_n||^2 per point — same sequential non-FMA order over ascending channel.
// Point n=(b,hw); channel stride is HW in NCHW. Loads coalesce across threads.
// ---------------------------------------------------------------------------
__global__ void znorm_kernel(const float* __restrict__ z) {
    int n  = blockIdx.x * 256 + threadIdx.x;  // grid 256 x 256 -> 65536
    int b  = n >> 12;
    int hw = n & 4095;
    const float* p = z + (size_t)b * Cc * HW + hw;
    float s = 0.f;
#pragma unroll 8
    for (int c = 0; c < Cc; ++c) {
        float v = p[(size_t)c * HW];
        s = __fadd_rn(s, __fmul_rn(v, v));
    }
    g_znorm[n] = s;
}

// ---------------------------------------------------------------------------
// Main fused kernel. Distance replicates the reference's fp32 rounding chain:
//   dot  = sequential fmaf over ascending c  (== Eigen gemm microkernel)
//   d    = fsub( fadd(zn, cn), fmul(2, dot) )   (== (zs+cs) - 2*mm in XLA)
// Argmin: strict '<' over ascending k per thread + lexicographic (d, idx)
// cross-thread == jnp.argmin first-occurrence semantics.
// 256 threads = 16 (m-groups) x 16 (k-groups); thread tile 8m x 4k.
// ---------------------------------------------------------------------------
__global__ __launch_bounds__(256, 2) void vq_kernel(
    const float* __restrict__ z, const float* __restrict__ cb,
    float* __restrict__ out, int out_size)
{
    __shared__ float zsc[32 * 128];   // [c-chunk 32][m 128]   (16 KB)
    __shared__ float cs[32 * 65];     // [c-chunk 32][k 64 +1 pad] (8.3 KB)
    __shared__ float zn_s[BM];
    __shared__ int   idx_s[BM];
    __shared__ float wsum[8];

    // reduction arrays overlay zsc after the compute phase
    float* red_d = zsc;                  // [128][16] floats  (zsc[0..2047])
    int*   red_i = (int*)(zsc + 2048);   // [128][16] ints    (zsc[2048..4095])

    const int tid  = threadIdx.x;
    const int tx   = tid & 15;     // m group: points tx*4..tx*4+3 and +64
    const int ty   = tid >> 4;     // k group: codes ty*4..ty*4+3 in chunk
    const int warp = tid >> 5;
    const int lane = tid & 31;

    const int n0  = blockIdx.x * BM;
    const int b   = n0 >> 12;      // block never straddles a batch
    const int hw0 = n0 & 4095;
    const float* zb = z + (size_t)b * Cc * HW + hw0;

    // per-point ||z||^2 into smem (visible after first __syncthreads below)
    if (tid < BM) zn_s[tid] = g_znorm[n0 + tid];

    float best[8];
    int   bidx[8];
#pragma unroll
    for (int i = 0; i < 8; ++i) { best[i] = CUDART_INF_F; bidx[i] = 0; }

    for (int kc = 0; kc < 16; ++kc) {
        const int k0 = kc * 64;
        float acc[8][4];
#pragma unroll
        for (int mi = 0; mi < 8; ++mi)
#pragma unroll
            for (int ki = 0; ki < 4; ++ki) acc[mi][ki] = 0.f;

        for (int cc = 0; cc < 8; ++cc) {           // C chunks of 32, ascending
            __syncthreads();
            // load z chunk [32 c][128 m], coalesced (points contiguous in hw)
            for (int cr = warp; cr < 32; cr += 8) {
                float4 v = *(const float4*)(zb + (size_t)(cc * 32 + cr) * HW + lane * 4);
                *(float4*)&zsc[cr * 128 + lane * 4] = v;
            }
            // load codebook chunk transposed -> cs[c][k] (padded rows, 65)
            for (int t = tid; t < 64 * 8; t += 256) {
                int k  = t >> 3;
                int c4 = (t & 7) * 4;
                float4 v = *(const float4*)(cb + (size_t)(k0 + k) * Cc + cc * 32 + c4);
                cs[(c4 + 0) * 65 + k] = v.x;
                cs[(c4 + 1) * 65 + k] = v.y;
                cs[(c4 + 2) * 65 + k] = v.z;
                cs[(c4 + 3) * 65 + k] = v.w;
            }
            __syncthreads();

            // sequential single-accumulator fmaf, ascending global c:
            // bitwise identical to Eigen's gemm inner loop.
#pragma unroll 8
            for (int c = 0; c < 32; ++c) {
                float4 z0 = *(float4*)&zsc[c * 128 + tx * 4];
                float4 z1 = *(float4*)&zsc[c * 128 + 64 + tx * 4];
                float zf[8] = {z0.x, z0.y, z0.z, z0.w, z1.x, z1.y, z1.z, z1.w};
                float cf[4];
#pragma unroll
                for (int ki = 0; ki < 4; ++ki) cf[ki] = cs[c * 65 + ty * 4 + ki];
#pragma unroll
                for (int mi = 0; mi < 8; ++mi)
#pragma unroll
                    for (int ki = 0; ki < 4; ++ki)
                        acc[mi][ki] = fmaf(zf[mi], cf[ki], acc[mi][ki]);
            }
        }

        // chunk epilogue: d = (zn + cn) - 2*dot with the reference's exact
        // fp32 rounding chain (ulp(~256) tie grid). Strict '<' keeps lowest k
        // (per-thread k sequence is strictly ascending).
#pragma unroll
        for (int ki = 0; ki < 4; ++ki) {
            int k = k0 + ty * 4 + ki;
            float cn = g_cnorm[k];
#pragma unroll
            for (int mi = 0; mi < 8; ++mi) {
                int m = (mi < 4) ? (tx * 4 + mi) : (64 + tx * 4 + (mi - 4));
                float t1 = __fadd_rn(zn_s[m], cn);
                float d  = __fsub_rn(t1, __fmul_rn(2.0f, acc[mi][ki]));
                if (d < best[mi]) { best[mi] = d; bidx[mi] = k; }
            }
        }
    }

    // cross-thread (over ty) argmin reduction, lexicographic (d, idx)
    __syncthreads();
#pragma unroll
    for (int mi = 0; mi < 8; ++mi) {
        int m = (mi < 4) ? (tx * 4 + mi) : (64 + tx * 4 + (mi - 4));
        red_d[m * 16 + ty] = best[mi];
        red_i[m * 16 + ty] = bidx[mi];
    }
    __syncthreads();
    if (tid < BM) {
        int m = tid;
        float bd = red_d[m * 16];
        int   bi = red_i[m * 16];
#pragma unroll
        for (int t = 1; t < 16; ++t) {
            float d  = red_d[m * 16 + t];
            int   i2 = red_i[m * 16 + t];
            if (d < bd || (d == bd && i2 < bi)) { bd = d; bi = i2; }
        }
        idx_s[m] = bi;
        if (out_size >= NZQ + NPTS)
            out[NZQ + n0 + m] = (float)bi;
    }
    __syncthreads();

    // gather zq; straight-through output zc + (zq - zc) with fp32 rounding
    // exactly as the reference; accumulate loss partial.
    float lsum = 0.f;
    const bool wq = (out_size >= NZQ);
    float* outb = out + (size_t)b * Cc * HW + hw0;
    for (int c = warp; c < Cc; c += 8) {
#pragma unroll
        for (int j = 0; j < 4; ++j) {
            int mm = lane + j * 32;
            float q  = cb[(size_t)idx_s[mm] * Cc + c];
            float zv = zb[(size_t)c * HW + mm];
            float df = __fsub_rn(q, zv);
            lsum = fmaf(df, df, lsum);
            if (wq) outb[(size_t)c * HW + mm] = __fadd_rn(zv, df);
        }
    }
#pragma unroll
    for (int o = 16; o > 0; o >>= 1)
        lsum += __shfl_down_sync(0xffffffffu, lsum, o);
    if (lane == 0) wsum[warp] = lsum;
    __syncthreads();
    if (tid == 0) {
        float s = 0.f;
#pragma unroll
        for (int w = 0; w < 8; ++w) s += wsum[w];
        g_partial[blockIdx.x] = s;
    }
}

// ---------------------------------------------------------------------------
// Deterministic loss finalize: loss = (1 - 0.25) * mean((zq - z)^2)
// ---------------------------------------------------------------------------
__global__ void fin_kernel(float* __restrict__ out, int out_size) {
    if (threadIdx.x == 0 && out_size >= NZQ + NPTS + 1) {
        float s = 0.f;
        for (int i = 0; i < NBLK; ++i) s += g_partial[i];
        out[NZQ + NPTS] = 0.75f * (s * (1.0f / 16777216.0f));
    }
}

// ---------------------------------------------------------------------------
extern "C" void kernel_launch(void* const* d_in, const int* in_sizes, int n_in,
                              void* d_out, int out_size) {
    const float* z  = (const float*)d_in[0];   // [16,256,64,64]
    const float* cb = (const float*)d_in[1];   // [1024,256]
    float* out = (float*)d_out;

    cnorm_kernel<<<4, 256>>>(cb);
    znorm_kernel<<<256, 256>>>(z);
    vq_kernel<<<NBLK, 256>>>(z, cb, out, out_size);
    fin_kernel<<<1, 32>>>(out, out_size);
}